// round 15
// baseline (speedup 1.0000x reference)
#include <cuda_runtime.h>
#include <cuda_bf16.h>

// Model: x[n,t,:] = [features[n,0..11], AVG[t]]  (T=120, F=13)
// h1 = LSTM(H=30)(x);  out = LSTM(H=1)(h1)
//
// Warp = 2 sequences; lane halves: lanes 0-15 seq A, 16-31 seq B.
//   sub-lane sl<15 owns LSTM1 units {2sl, 2sl+1} of its sequence
//   (weight regs: 2 units x 4 gates x 15 k-pairs = 120 u64 — same total
//    footprint as 1-unit-per-lane, but 8 independent fma2 chains and 2
//    independent activation blocks per lane -> 2x in-warp ILP).
//   sl==15 owns LSTM2 of its sequence in unit-slot 0 (W_ih2 in the matvec
//   slots; recurrent term folded via per-lane wq/bq constants, exact +0
//   elsewhere). h broadcast via per-warp double-buffered smem rows:
//   pair m of half h at byte offset 16m + 8h (adjacent banks, conflict-free).
//   Activations: __expf-based (R14 showed tanh.approx expands/emulates here).

#define TT   120
#define HH   30
#define FEAT 12
#define NPAIR 15

typedef unsigned long long u64;

__constant__ float AVG_c[TT] = {
    0.0256f,0.0823f,0.1157f,0.1315f,0.1366f,0.1369f,0.1347f,0.1308f,0.1259f,0.1205f,
    0.1146f,0.1086f,0.1028f,0.0970f,0.0913f,0.0858f,0.0805f,0.0756f,0.0708f,0.0664f,
    0.0623f,0.0584f,0.0549f,0.0515f,0.0485f,0.0456f,0.0429f,0.0404f,0.0381f,0.0360f,
    0.0340f,0.0321f,0.0304f,0.0287f,0.0272f,0.0258f,0.0245f,0.0233f,0.0222f,0.0211f,
    0.0201f,0.0191f,0.0182f,0.0173f,0.0165f,0.0158f,0.0150f,0.0143f,0.0137f,0.0130f,
    0.0125f,0.0119f,0.0114f,0.0108f,0.0104f,0.0099f,0.0095f,0.0091f,0.0087f,0.0083f,
    0.0080f,0.0077f,0.0074f,0.0071f,0.0068f,0.0065f,0.0062f,0.0060f,0.0058f,0.0055f,
    0.0053f,0.0050f,0.0049f,0.0047f,0.0045f,0.0044f,0.0042f,0.0040f,0.0039f,0.0038f,
    0.0036f,0.0034f,0.0033f,0.0032f,0.0031f,0.0030f,0.0029f,0.0028f,0.0027f,0.0026f,
    0.0025f,0.0024f,0.0023f,0.0022f,0.0021f,0.0021f,0.0020f,0.0019f,0.0018f,0.0018f,
    0.0017f,0.0017f,0.0016f,0.0016f,0.0015f,0.0015f,0.0014f,0.0014f,0.0013f,0.0013f,
    0.0013f,0.0012f,0.0012f,0.0011f,0.0011f,0.0011f,0.0010f,0.0010f,0.0010f,0.0009f
};

// ---- packed f32x2 helpers (Blackwell) ----
__device__ __forceinline__ u64 pack2(float lo, float hi) {
    u64 d; asm("mov.b64 %0, {%1, %2};" : "=l"(d) : "f"(lo), "f"(hi)); return d;
}
__device__ __forceinline__ void unpack2(u64 v, float& lo, float& hi) {
    asm("mov.b64 {%0, %1}, %2;" : "=f"(lo), "=f"(hi) : "l"(v));
}
__device__ __forceinline__ u64 fma2(u64 a, u64 b, u64 c) {
    u64 d; asm("fma.rn.f32x2 %0, %1, %2, %3;" : "=l"(d) : "l"(a), "l"(b), "l"(c)); return d;
}

__device__ __forceinline__ float sigmoid_f(float x) {
    float e = __expf(-x);
    return __fdividef(1.0f, 1.0f + e);
}
__device__ __forceinline__ float tanh_f(float x) {
    float e = __expf(2.0f * x);
    return 1.0f - __fdividef(2.0f, 1.0f + e);
}

__global__ __launch_bounds__(128, 3)
void lstm_trace_kernel(const float* __restrict__ features,
                       const float* __restrict__ w_ih1,   // [120,13]
                       const float* __restrict__ w_hh1,   // [120,30]
                       const float* __restrict__ b1,      // [120]
                       const float* __restrict__ w_ih2,   // [4,30]
                       const float* __restrict__ w_hh2,   // [4,1]
                       const float* __restrict__ b2,      // [4]
                       float* __restrict__ out,           // [N,120]
                       int N)
{
    // per-warp double-buffered h rows; within a buffer: pair m of half h
    // lives at float index 4m + 2h (byte 16m + 8h) -> conflict-free LDS/STS.64
    __shared__ __align__(16) float hbuf[4][2][64];

    const int warp_in_blk = threadIdx.x >> 5;
    const int warp_id  = blockIdx.x * 4 + warp_in_blk;
    const int lane     = threadIdx.x & 31;
    const int half     = lane >> 4;        // 0: seq A, 1: seq B
    const int sl       = lane & 15;        // sub-lane within half
    const int seq      = warp_id * 2 + half;
    const int nwseq    = warp_id * 2;      // first seq of this warp
    if (nwseq >= N) return;
    const bool seq_ok  = (seq < N);
    const int seqs     = seq_ok ? seq : nwseq;

    const float* feat = features + seqs * FEAT;

    // ---- per-lane weights: 2 unit-slots x 4 gates x 15 k-pairs ----
    u64 w0i[NPAIR], w0f[NPAIR], w0g[NPAIR], w0o[NPAIR];   // unit u0 = 2*sl (or LSTM2 if sl==15)
    u64 w1i[NPAIR], w1f[NPAIR], w1g[NPAIR], w1o[NPAIR];   // unit u1 = 2*sl+1 (zero if sl==15)
    float b0i = 0.f, b0f = 0.f, b0g = 0.f, b0o = 0.f;     // base (input proj + bias), slot 0
    float b1i_ = 0.f, b1f_ = 0.f, b1g_ = 0.f, b1o_ = 0.f; // slot 1
    float t0i = 0.f, t0f = 0.f, t0g = 0.f, t0o = 0.f;     // trace-channel weights, slot 0
    float t1i = 0.f, t1f = 0.f, t1g = 0.f, t1o = 0.f;     // slot 1
    float wq_i = 0.f, wq_f = 0.f, wq_g = 0.f, wq_o = 0.f; // LSTM2 recurrent (sl==15 only)
    float bq_i = 0.f, bq_f = 0.f, bq_g = 0.f, bq_o = 0.f; // LSTM2 bias     (sl==15 only)

    if (sl < NPAIR) {
        const int u0 = 2 * sl, u1 = 2 * sl + 1;
        const float* r0i = w_hh1 + (0 * HH + u0) * HH;
        const float* r0f = w_hh1 + (1 * HH + u0) * HH;
        const float* r0g = w_hh1 + (2 * HH + u0) * HH;
        const float* r0o = w_hh1 + (3 * HH + u0) * HH;
        const float* r1i = w_hh1 + (0 * HH + u1) * HH;
        const float* r1f = w_hh1 + (1 * HH + u1) * HH;
        const float* r1g = w_hh1 + (2 * HH + u1) * HH;
        const float* r1o = w_hh1 + (3 * HH + u1) * HH;
        #pragma unroll
        for (int m = 0; m < NPAIR; m++) {
            w0i[m] = pack2(r0i[2 * m], r0i[2 * m + 1]);
            w0f[m] = pack2(r0f[2 * m], r0f[2 * m + 1]);
            w0g[m] = pack2(r0g[2 * m], r0g[2 * m + 1]);
            w0o[m] = pack2(r0o[2 * m], r0o[2 * m + 1]);
            w1i[m] = pack2(r1i[2 * m], r1i[2 * m + 1]);
            w1f[m] = pack2(r1f[2 * m], r1f[2 * m + 1]);
            w1g[m] = pack2(r1g[2 * m], r1g[2 * m + 1]);
            w1o[m] = pack2(r1o[2 * m], r1o[2 * m + 1]);
        }
        const float* p0i = w_ih1 + (0 * HH + u0) * (FEAT + 1);
        const float* p0f = w_ih1 + (1 * HH + u0) * (FEAT + 1);
        const float* p0g = w_ih1 + (2 * HH + u0) * (FEAT + 1);
        const float* p0o = w_ih1 + (3 * HH + u0) * (FEAT + 1);
        const float* p1i = w_ih1 + (0 * HH + u1) * (FEAT + 1);
        const float* p1f = w_ih1 + (1 * HH + u1) * (FEAT + 1);
        const float* p1g = w_ih1 + (2 * HH + u1) * (FEAT + 1);
        const float* p1o = w_ih1 + (3 * HH + u1) * (FEAT + 1);
        b0i = b1[0 * HH + u0]; b0f = b1[1 * HH + u0];
        b0g = b1[2 * HH + u0]; b0o = b1[3 * HH + u0];
        b1i_ = b1[0 * HH + u1]; b1f_ = b1[1 * HH + u1];
        b1g_ = b1[2 * HH + u1]; b1o_ = b1[3 * HH + u1];
        #pragma unroll
        for (int d = 0; d < FEAT; d++) {
            float fd = feat[d];
            b0i = fmaf(fd, p0i[d], b0i);  b0f = fmaf(fd, p0f[d], b0f);
            b0g = fmaf(fd, p0g[d], b0g);  b0o = fmaf(fd, p0o[d], b0o);
            b1i_ = fmaf(fd, p1i[d], b1i_); b1f_ = fmaf(fd, p1f[d], b1f_);
            b1g_ = fmaf(fd, p1g[d], b1g_); b1o_ = fmaf(fd, p1o[d], b1o_);
        }
        t0i = p0i[FEAT]; t0f = p0f[FEAT]; t0g = p0g[FEAT]; t0o = p0o[FEAT];
        t1i = p1i[FEAT]; t1f = p1f[FEAT]; t1g = p1g[FEAT]; t1o = p1o[FEAT];
    } else {
        // sl == 15: LSTM2 in slot 0; slot 1 zeroed
        #pragma unroll
        for (int m = 0; m < NPAIR; m++) {
            w0i[m] = pack2(w_ih2[0 * HH + 2 * m], w_ih2[0 * HH + 2 * m + 1]);
            w0f[m] = pack2(w_ih2[1 * HH + 2 * m], w_ih2[1 * HH + 2 * m + 1]);
            w0g[m] = pack2(w_ih2[2 * HH + 2 * m], w_ih2[2 * HH + 2 * m + 1]);
            w0o[m] = pack2(w_ih2[3 * HH + 2 * m], w_ih2[3 * HH + 2 * m + 1]);
            w1i[m] = 0ull; w1f[m] = 0ull; w1g[m] = 0ull; w1o[m] = 0ull;
        }
        wq_i = w_hh2[0]; wq_f = w_hh2[1]; wq_g = w_hh2[2]; wq_o = w_hh2[3];
        bq_i = b2[0];    bq_f = b2[1];    bq_g = b2[2];    bq_o = b2[3];
    }

    float* row0 = &hbuf[warp_in_blk][0][0];
    float* row1 = &hbuf[warp_in_blk][1][0];

    // zero the t=0 read buffer (buffer 0); each lane owns float slots 4sl+2h..+1
    {
        const int idx = 4 * sl + 2 * half;
        row0[idx] = 0.f; row0[idx + 1] = 0.f;
    }
    __syncwarp();

    float c0 = 0.f, c1u = 0.f;   // cell states of unit slots 0,1 (slot0 on sl==15: c2)
    float h0p = 0.f;             // prev h of slot 0 (sl==15: h2 prev) for LSTM2 recurrent
    float* outp = out + seqs * TT;
    const bool is2 = (sl == NPAIR);   // LSTM2 lane
    const int hofs = 2 * half;        // float offset of this half within a pair slot

    #pragma unroll 1
    for (int t = 0; t < TT; t++) {
        float* rrow = (t & 1) ? row1 : row0;
        float* wrow = (t & 1) ? row0 : row1;
        const float at = AVG_c[t];

        u64 a0i = pack2(fmaf(at, t0i, b0i), 0.f);
        u64 a0f = pack2(fmaf(at, t0f, b0f), 0.f);
        u64 a0g = pack2(fmaf(at, t0g, b0g), 0.f);
        u64 a0o = pack2(fmaf(at, t0o, b0o), 0.f);
        u64 a1i = pack2(fmaf(at, t1i, b1i_), 0.f);
        u64 a1f = pack2(fmaf(at, t1f, b1f_), 0.f);
        u64 a1g = pack2(fmaf(at, t1g, b1g_), 0.f);
        u64 a1o = pack2(fmaf(at, t1o, b1o_), 0.f);
        #pragma unroll
        for (int m = 0; m < NPAIR; m++) {
            const u64 hp = *reinterpret_cast<const u64*>(&rrow[4 * m + hofs]);  // LDS.64
            a0i = fma2(hp, w0i[m], a0i);
            a0f = fma2(hp, w0f[m], a0f);
            a0g = fma2(hp, w0g[m], a0g);
            a0o = fma2(hp, w0o[m], a0o);
            a1i = fma2(hp, w1i[m], a1i);
            a1f = fma2(hp, w1f[m], a1f);
            a1g = fma2(hp, w1g[m], a1g);
            a1o = fma2(hp, w1o[m], a1o);
        }
        float g0i, g0f, g0g, g0o, g1i, g1f, g1g, g1o, x0, x1, x2, x3, y0, y1, y2, y3;
        unpack2(a0i, g0i, x0); g0i += x0;
        unpack2(a0f, g0f, x1); g0f += x1;
        unpack2(a0g, g0g, x2); g0g += x2;
        unpack2(a0o, g0o, x3); g0o += x3;
        unpack2(a1i, g1i, y0); g1i += y0;
        unpack2(a1f, g1f, y1); g1f += y1;
        unpack2(a1g, g1g, y2); g1g += y2;
        unpack2(a1o, g1o, y3); g1o += y3;

        // unified adjustment (exact +0 except LSTM2 lane slot 0)
        g0i += fmaf(wq_i, h0p, bq_i);
        g0f += fmaf(wq_f, h0p, bq_f);
        g0g += fmaf(wq_g, h0p, bq_g);
        g0o += fmaf(wq_o, h0p, bq_o);

        // activation blocks (two independent chains)
        float cn0 = sigmoid_f(g0f) * c0 + sigmoid_f(g0i) * tanh_f(g0g);
        float hn0 = sigmoid_f(g0o) * tanh_f(cn0);
        float cn1 = sigmoid_f(g1f) * c1u + sigmoid_f(g1i) * tanh_f(g1g);
        float hn1 = sigmoid_f(g1o) * tanh_f(cn1);

        // LSTM2 lane: t=0 update is bogus (first real step is t=1) -> reset
        if (t == 0 && is2) { cn0 = 0.f; hn0 = 0.f; }
        c0 = cn0; c1u = cn1;

        // store h2[t-1] (LSTM2 pipeline one step behind)
        if (t > 0 && is2 && seq_ok) outp[t - 1] = hn0;
        h0p = hn0;

        // publish packed unit pair (sl==15 writes unread slot 15)
        *reinterpret_cast<u64*>(&wrow[4 * sl + hofs]) = pack2(hn0, hn1);
        __syncwarp();
    }

    // ---- epilogue: LSTM2 step 119 using h1[119] (final h in buffer 0) ----
    {
        u64 a0i = 0ull, a0f = 0ull, a0g = 0ull, a0o = 0ull;
        #pragma unroll
        for (int m = 0; m < NPAIR; m++) {
            const u64 hp = *reinterpret_cast<const u64*>(&row0[4 * m + hofs]);
            a0i = fma2(hp, w0i[m], a0i);
            a0f = fma2(hp, w0f[m], a0f);
            a0g = fma2(hp, w0g[m], a0g);
            a0o = fma2(hp, w0o[m], a0o);
        }
        float gi, gf, gg, go, x0, x1, x2, x3;
        unpack2(a0i, gi, x0); gi += x0;
        unpack2(a0f, gf, x1); gf += x1;
        unpack2(a0g, gg, x2); gg += x2;
        unpack2(a0o, go, x3); go += x3;

        gi += fmaf(wq_i, h0p, bq_i);
        gf += fmaf(wq_f, h0p, bq_f);
        gg += fmaf(wq_g, h0p, bq_g);
        go += fmaf(wq_o, h0p, bq_o);

        float cn = sigmoid_f(gf) * c0 + sigmoid_f(gi) * tanh_f(gg);
        float hn = sigmoid_f(go) * tanh_f(cn);
        if (is2 && seq_ok) outp[TT - 1] = hn;
    }
}

extern "C" void kernel_launch(void* const* d_in, const int* in_sizes, int n_in,
                              void* d_out, int out_size) {
    const float* features = (const float*)d_in[0];
    const float* w_ih1    = (const float*)d_in[1];
    const float* w_hh1    = (const float*)d_in[2];
    const float* b1       = (const float*)d_in[3];
    const float* w_ih2    = (const float*)d_in[4];
    const float* w_hh2    = (const float*)d_in[5];
    const float* b2       = (const float*)d_in[6];
    float* out = (float*)d_out;

    const int N = in_sizes[0] / FEAT;                 // 32768
    const int n_warps = (N + 1) / 2;                  // 2 sequences per warp
    const int threads = 128;                          // 4 warps/block, 3 CTAs/SM
    const int blocks  = (n_warps + 3) / 4;

    lstm_trace_kernel<<<blocks, threads>>>(features, w_ih1, w_hh1, b1,
                                           w_ih2, w_hh2, b2, out, N);
}

// round 16
// speedup vs baseline: 2.1159x; 2.1159x over previous
#include <cuda_runtime.h>
#include <cuda_bf16.h>

// Model: x[n,t,:] = [features[n,0..11], AVG[t]]  (T=120, F=13)
// h1 = LSTM(H=30)(x);  out = LSTM(H=1)(h1)
//
// Warp = 2 sequences (A,B) SHARING one set of weight registers:
//   lane u<30 owns LSTM1 unit u; its 4 gate rows, k-pair-packed f32x2,
//   are 60 u64 = 120 regs TOTAL (unchanged from the 1-seq champion).
//   Each lane runs unit u's matvec + activation for BOTH sequences
//   (interleaved -> two independent ~800-cyc chains per warp fill the
//   latency that capped the 1-seq version at issue=53%).
//   lane 30 = LSTM2 of seq A (A-side accumulators are W_ih2·hA),
//   lane 31 = LSTM2 of seq B (same weights, B-side accumulators);
//   recurrent terms folded via wq/bq constants (exact +0 on lanes<30).
//   h broadcast: per-warp double-buffered smem rows per seq, LDS.64 pairs.
//   Per-seq input-projection bases live in smem float4 (reg relief).

#define TT   120
#define HH   30
#define FEAT 12
#define NPAIR 15

typedef unsigned long long u64;

__constant__ float AVG_c[TT] = {
    0.0256f,0.0823f,0.1157f,0.1315f,0.1366f,0.1369f,0.1347f,0.1308f,0.1259f,0.1205f,
    0.1146f,0.1086f,0.1028f,0.0970f,0.0913f,0.0858f,0.0805f,0.0756f,0.0708f,0.0664f,
    0.0623f,0.0584f,0.0549f,0.0515f,0.0485f,0.0456f,0.0429f,0.0404f,0.0381f,0.0360f,
    0.0340f,0.0321f,0.0304f,0.0287f,0.0272f,0.0258f,0.0245f,0.0233f,0.0222f,0.0211f,
    0.0201f,0.0191f,0.0182f,0.0173f,0.0165f,0.0158f,0.0150f,0.0143f,0.0137f,0.0130f,
    0.0125f,0.0119f,0.0114f,0.0108f,0.0104f,0.0099f,0.0095f,0.0091f,0.0087f,0.0083f,
    0.0080f,0.0077f,0.0074f,0.0071f,0.0068f,0.0065f,0.0062f,0.0060f,0.0058f,0.0055f,
    0.0053f,0.0050f,0.0049f,0.0047f,0.0045f,0.0044f,0.0042f,0.0040f,0.0039f,0.0038f,
    0.0036f,0.0034f,0.0033f,0.0032f,0.0031f,0.0030f,0.0029f,0.0028f,0.0027f,0.0026f,
    0.0025f,0.0024f,0.0023f,0.0022f,0.0021f,0.0021f,0.0020f,0.0019f,0.0018f,0.0018f,
    0.0017f,0.0017f,0.0016f,0.0016f,0.0015f,0.0015f,0.0014f,0.0014f,0.0013f,0.0013f,
    0.0013f,0.0012f,0.0012f,0.0011f,0.0011f,0.0011f,0.0010f,0.0010f,0.0010f,0.0009f
};

// ---- packed f32x2 helpers (Blackwell) ----
__device__ __forceinline__ u64 pack2(float lo, float hi) {
    u64 d; asm("mov.b64 %0, {%1, %2};" : "=l"(d) : "f"(lo), "f"(hi)); return d;
}
__device__ __forceinline__ void unpack2(u64 v, float& lo, float& hi) {
    asm("mov.b64 {%0, %1}, %2;" : "=f"(lo), "=f"(hi) : "l"(v));
}
__device__ __forceinline__ u64 fma2(u64 a, u64 b, u64 c) {
    u64 d; asm("fma.rn.f32x2 %0, %1, %2, %3;" : "=l"(d) : "l"(a), "l"(b), "l"(c)); return d;
}

__device__ __forceinline__ float sigmoid_f(float x) {
    float e = __expf(-x);
    return __fdividef(1.0f, 1.0f + e);
}
__device__ __forceinline__ float tanh_f(float x) {
    float e = __expf(2.0f * x);
    return 1.0f - __fdividef(2.0f, 1.0f + e);
}

__global__ __launch_bounds__(128, 3)
void lstm_trace_kernel(const float* __restrict__ features,
                       const float* __restrict__ w_ih1,   // [120,13]
                       const float* __restrict__ w_hh1,   // [120,30]
                       const float* __restrict__ b1,      // [120]
                       const float* __restrict__ w_ih2,   // [4,30]
                       const float* __restrict__ w_hh2,   // [4,1]
                       const float* __restrict__ b2,      // [4]
                       float* __restrict__ out,           // [N,120]
                       int N)
{
    // h rows: [warp][buffer][seq][32] floats
    __shared__ __align__(16) float hbuf[4][2][2][32];
    // per-seq input-projection bases: [warp][seq][lane] float4
    __shared__ __align__(16) float4 bbuf[4][2][32];

    const int warp_in_blk = threadIdx.x >> 5;
    const int warp_id  = blockIdx.x * 4 + warp_in_blk;
    const int lane     = threadIdx.x & 31;
    const int seqA = warp_id * 2;
    const int seqB = seqA + 1;
    if (seqA >= N) return;
    const bool hasB = (seqB < N);
    const int seqBs = hasB ? seqB : seqA;

    // ---- per-lane k-pair-packed weights (shared by both sequences) ----
    u64 wi[NPAIR], wf[NPAIR], wg[NPAIR], wo[NPAIR];
    float w12_i = 0.f, w12_f = 0.f, w12_g = 0.f, w12_o = 0.f;
    float wq_i = 0.f, wq_f = 0.f, wq_g = 0.f, wq_o = 0.f;  // LSTM2 recurrent (lanes 30,31)
    float bq_i = 0.f, bq_f = 0.f, bq_g = 0.f, bq_o = 0.f;  // LSTM2 bias      (lanes 30,31)

    if (lane < HH) {
        const float* ri = w_hh1 + (0 * HH + lane) * HH;
        const float* rf = w_hh1 + (1 * HH + lane) * HH;
        const float* rg = w_hh1 + (2 * HH + lane) * HH;
        const float* ro = w_hh1 + (3 * HH + lane) * HH;
        #pragma unroll
        for (int m = 0; m < NPAIR; m++) {
            wi[m] = pack2(ri[2 * m], ri[2 * m + 1]);
            wf[m] = pack2(rf[2 * m], rf[2 * m + 1]);
            wg[m] = pack2(rg[2 * m], rg[2 * m + 1]);
            wo[m] = pack2(ro[2 * m], ro[2 * m + 1]);
        }
        const float* pi = w_ih1 + (0 * HH + lane) * (FEAT + 1);
        const float* pf = w_ih1 + (1 * HH + lane) * (FEAT + 1);
        const float* pg = w_ih1 + (2 * HH + lane) * (FEAT + 1);
        const float* po = w_ih1 + (3 * HH + lane) * (FEAT + 1);
        // bases for both sequences -> smem
        const float* fA = features + seqA  * FEAT;
        const float* fB = features + seqBs * FEAT;
        float ai = b1[0 * HH + lane], af = b1[1 * HH + lane];
        float ag = b1[2 * HH + lane], ao = b1[3 * HH + lane];
        float bi = ai, bf = af, bg = ag, bo = ao;
        #pragma unroll
        for (int d = 0; d < FEAT; d++) {
            float fa = fA[d], fb = fB[d];
            ai = fmaf(fa, pi[d], ai);  bi = fmaf(fb, pi[d], bi);
            af = fmaf(fa, pf[d], af);  bf = fmaf(fb, pf[d], bf);
            ag = fmaf(fa, pg[d], ag);  bg = fmaf(fb, pg[d], bg);
            ao = fmaf(fa, po[d], ao);  bo = fmaf(fb, po[d], bo);
        }
        bbuf[warp_in_blk][0][lane] = make_float4(ai, af, ag, ao);
        bbuf[warp_in_blk][1][lane] = make_float4(bi, bf, bg, bo);
        w12_i = pi[FEAT]; w12_f = pf[FEAT]; w12_g = pg[FEAT]; w12_o = po[FEAT];
    } else {
        // lanes 30 and 31: LSTM2 weights (lane 30 uses A-side, 31 uses B-side)
        #pragma unroll
        for (int m = 0; m < NPAIR; m++) {
            wi[m] = pack2(w_ih2[0 * HH + 2 * m], w_ih2[0 * HH + 2 * m + 1]);
            wf[m] = pack2(w_ih2[1 * HH + 2 * m], w_ih2[1 * HH + 2 * m + 1]);
            wg[m] = pack2(w_ih2[2 * HH + 2 * m], w_ih2[2 * HH + 2 * m + 1]);
            wo[m] = pack2(w_ih2[3 * HH + 2 * m], w_ih2[3 * HH + 2 * m + 1]);
        }
        wq_i = w_hh2[0]; wq_f = w_hh2[1]; wq_g = w_hh2[2]; wq_o = w_hh2[3];
        bq_i = b2[0];    bq_f = b2[1];    bq_g = b2[2];    bq_o = b2[3];
        bbuf[warp_in_blk][0][lane] = make_float4(0.f, 0.f, 0.f, 0.f);
        bbuf[warp_in_blk][1][lane] = make_float4(0.f, 0.f, 0.f, 0.f);
    }

    float* rA0 = &hbuf[warp_in_blk][0][0][0];
    float* rB0 = &hbuf[warp_in_blk][0][1][0];
    float* rA1 = &hbuf[warp_in_blk][1][0][0];
    float* rB1 = &hbuf[warp_in_blk][1][1][0];
    const float4* baseA = &bbuf[warp_in_blk][0][lane];
    const float4* baseB = &bbuf[warp_in_blk][1][lane];

    rA0[lane] = 0.f;
    rB0[lane] = 0.f;
    __syncwarp();

    float cA = 0.f, cB = 0.f;     // cell states (lane30: c2 of A; lane31: chain-B = c2 of B)
    float hsA = 0.f, hsB = 0.f;   // prev h (for LSTM2 recurrent on lanes 30/31)
    const bool isA2 = (lane == 30);
    const bool isB2 = (lane == 31);
    float* outpA = out + seqA  * TT;
    float* outpB = out + seqBs * TT;

    #pragma unroll 1
    for (int t = 0; t < TT; t++) {
        const float* rrA = (t & 1) ? rA1 : rA0;
        const float* rrB = (t & 1) ? rB1 : rB0;
        float* wrA = (t & 1) ? rA0 : rA1;
        float* wrB = (t & 1) ? rB0 : rB1;
        const float at = AVG_c[t];

        float4 bA = *baseA;
        float4 bB = *baseB;
        u64 aAi = pack2(fmaf(at, w12_i, bA.x), 0.f);
        u64 aAf = pack2(fmaf(at, w12_f, bA.y), 0.f);
        u64 aAg = pack2(fmaf(at, w12_g, bA.z), 0.f);
        u64 aAo = pack2(fmaf(at, w12_o, bA.w), 0.f);
        u64 aBi = pack2(fmaf(at, w12_i, bB.x), 0.f);
        u64 aBf = pack2(fmaf(at, w12_f, bB.y), 0.f);
        u64 aBg = pack2(fmaf(at, w12_g, bB.z), 0.f);
        u64 aBo = pack2(fmaf(at, w12_o, bB.w), 0.f);

        #pragma unroll
        for (int m = 0; m < NPAIR; m++) {
            const u64 hpA = *reinterpret_cast<const u64*>(&rrA[2 * m]);  // broadcast LDS.64
            const u64 hpB = *reinterpret_cast<const u64*>(&rrB[2 * m]);
            aAi = fma2(hpA, wi[m], aAi);
            aBi = fma2(hpB, wi[m], aBi);
            aAf = fma2(hpA, wf[m], aAf);
            aBf = fma2(hpB, wf[m], aBf);
            aAg = fma2(hpA, wg[m], aAg);
            aBg = fma2(hpB, wg[m], aBg);
            aAo = fma2(hpA, wo[m], aAo);
            aBo = fma2(hpB, wo[m], aBo);
        }
        float gAi, gAf, gAg, gAo, gBi, gBf, gBg, gBo;
        float x0, x1, x2, x3, y0, y1, y2, y3;
        unpack2(aAi, gAi, x0); gAi += x0;
        unpack2(aAf, gAf, x1); gAf += x1;
        unpack2(aAg, gAg, x2); gAg += x2;
        unpack2(aAo, gAo, x3); gAo += x3;
        unpack2(aBi, gBi, y0); gBi += y0;
        unpack2(aBf, gBf, y1); gBf += y1;
        unpack2(aBg, gBg, y2); gBg += y2;
        unpack2(aBo, gBo, y3); gBo += y3;

        // unified adjustment (exact +0 on lanes<30)
        gAi += fmaf(wq_i, hsA, bq_i);
        gAf += fmaf(wq_f, hsA, bq_f);
        gAg += fmaf(wq_g, hsA, bq_g);
        gAo += fmaf(wq_o, hsA, bq_o);
        gBi += fmaf(wq_i, hsB, bq_i);
        gBf += fmaf(wq_f, hsB, bq_f);
        gBg += fmaf(wq_g, hsB, bq_g);
        gBo += fmaf(wq_o, hsB, bq_o);

        // two independent activation chains
        float cnA = sigmoid_f(gAf) * cA + sigmoid_f(gAi) * tanh_f(gAg);
        float hnA = sigmoid_f(gAo) * tanh_f(cnA);
        float cnB = sigmoid_f(gBf) * cB + sigmoid_f(gBi) * tanh_f(gBg);
        float hnB = sigmoid_f(gBo) * tanh_f(cnB);

        // LSTM2 lanes: t=0 update is bogus (first real step is t=1) -> reset
        if (t == 0) {
            if (isA2) { cnA = 0.f; hnA = 0.f; }
            if (isB2) { cnB = 0.f; hnB = 0.f; }
        }
        cA = cnA; cB = cnB;

        // store h2[t-1] (LSTM2 pipeline one step behind)
        if (t > 0) {
            if (isA2) outpA[t - 1] = hnA;
            if (isB2 && hasB) outpB[t - 1] = hnB;
        }
        hsA = hnA; hsB = hnB;

        wrA[lane] = hnA;   // lanes 30/31 write unread slots
        wrB[lane] = hnB;
        __syncwarp();
    }

    // ---- epilogue: LSTM2 step 119 for both sequences (final h in buffer 0) ----
    {
        u64 aAi = 0ull, aAf = 0ull, aAg = 0ull, aAo = 0ull;
        u64 aBi = 0ull, aBf = 0ull, aBg = 0ull, aBo = 0ull;
        #pragma unroll
        for (int m = 0; m < NPAIR; m++) {
            const u64 hpA = *reinterpret_cast<const u64*>(&rA0[2 * m]);
            const u64 hpB = *reinterpret_cast<const u64*>(&rB0[2 * m]);
            aAi = fma2(hpA, wi[m], aAi);
            aBi = fma2(hpB, wi[m], aBi);
            aAf = fma2(hpA, wf[m], aAf);
            aBf = fma2(hpB, wf[m], aBf);
            aAg = fma2(hpA, wg[m], aAg);
            aBg = fma2(hpB, wg[m], aBg);
            aAo = fma2(hpA, wo[m], aAo);
            aBo = fma2(hpB, wo[m], aBo);
        }
        float gAi, gAf, gAg, gAo, gBi, gBf, gBg, gBo;
        float x0, x1, x2, x3, y0, y1, y2, y3;
        unpack2(aAi, gAi, x0); gAi += x0;
        unpack2(aAf, gAf, x1); gAf += x1;
        unpack2(aAg, gAg, x2); gAg += x2;
        unpack2(aAo, gAo, x3); gAo += x3;
        unpack2(aBi, gBi, y0); gBi += y0;
        unpack2(aBf, gBf, y1); gBf += y1;
        unpack2(aBg, gBg, y2); gBg += y2;
        unpack2(aBo, gBo, y3); gBo += y3;

        gAi += fmaf(wq_i, hsA, bq_i);
        gAf += fmaf(wq_f, hsA, bq_f);
        gAg += fmaf(wq_g, hsA, bq_g);
        gAo += fmaf(wq_o, hsA, bq_o);
        gBi += fmaf(wq_i, hsB, bq_i);
        gBf += fmaf(wq_f, hsB, bq_f);
        gBg += fmaf(wq_g, hsB, bq_g);
        gBo += fmaf(wq_o, hsB, bq_o);

        float cnA = sigmoid_f(gAf) * cA + sigmoid_f(gAi) * tanh_f(gAg);
        float hnA = sigmoid_f(gAo) * tanh_f(cnA);
        float cnB = sigmoid_f(gBf) * cB + sigmoid_f(gBi) * tanh_f(gBg);
        float hnB = sigmoid_f(gBo) * tanh_f(cnB);
        if (isA2) outpA[TT - 1] = hnA;
        if (isB2 && hasB) outpB[TT - 1] = hnB;
    }
}

extern "C" void kernel_launch(void* const* d_in, const int* in_sizes, int n_in,
                              void* d_out, int out_size) {
    const float* features = (const float*)d_in[0];
    const float* w_ih1    = (const float*)d_in[1];
    const float* w_hh1    = (const float*)d_in[2];
    const float* b1       = (const float*)d_in[3];
    const float* w_ih2    = (const float*)d_in[4];
    const float* w_hh2    = (const float*)d_in[5];
    const float* b2       = (const float*)d_in[6];
    float* out = (float*)d_out;

    const int N = in_sizes[0] / FEAT;                 // 32768
    const int n_warps = (N + 1) / 2;                  // 2 sequences per warp
    const int threads = 128;                          // 4 warps/block, 3 CTAs/SM
    const int blocks  = (n_warps + 3) / 4;

    lstm_trace_kernel<<<blocks, threads>>>(features, w_ih1, w_hh1, b1,
                                           w_ih2, w_hh2, b2, out, N);
}